// round 10
// baseline (speedup 1.0000x reference)
#include <cuda_runtime.h>

#define HH 2048
#define WW 2048
#define NB 148
#define NT 1024
#define NW 32
#define CBLK 74
#define TOT4 (HH*WW/4)          // 1,048,576 float4 per channel
#define STR (CBLK*NT)           // 75,776
#define SUB 32                  // band subgroup size
#define EPT 12                  // flag increment per launch (epochs used: 1..10)

// Scratch (device globals; no allocation allowed)
// slots 0,1: band double-buffer (first SUB entries); 2: phase0 per-block partials
__device__ float4 g_part[3][NB];
__device__ unsigned g_flag[NB];          // per-block monotone epoch flags (+EPT per launch)

__device__ __forceinline__ float neg_inf() { return __int_as_float(0xff800000); }
__device__ __forceinline__ float fmax4(float4 A) {
    return fmaxf(fmaxf(A.x, A.y), fmaxf(A.z, A.w));
}

// release store / acquire load on flag words (GPU scope)
__device__ __forceinline__ void st_rel(unsigned *p, unsigned v) {
    asm volatile("st.release.gpu.global.u32 [%0], %1;" :: "l"(p), "r"(v) : "memory");
}
__device__ __forceinline__ unsigned ld_acq(unsigned *p) {
    unsigned v;
    asm volatile("ld.acquire.gpu.global.u32 %0, [%1];" : "=r"(v) : "l"(p) : "memory");
    return v;
}

// Block-wide max, broadcast to ALL threads.
__device__ float block_max_bcast(float m) {
    __shared__ float sm[NW];
    __shared__ float sM;
    int tid = threadIdx.x;
    __syncthreads();                       // protect smem reuse across calls
    #pragma unroll
    for (int o = 16; o; o >>= 1) m = fmaxf(m, __shfl_xor_sync(0xffffffffu, m, o));
    if ((tid & 31) == 0) sm[tid >> 5] = m;
    __syncthreads();
    if (tid < 32) {
        float t = sm[tid];
        #pragma unroll
        for (int o = 16; o; o >>= 1) t = fmaxf(t, __shfl_xor_sync(0xffffffffu, t, o));
        if (tid == 0) sM = t;
    }
    __syncthreads();
    return sM;
}

// Block-wide 3-way sum; result valid on threads 0..31 (all lanes of warp 0).
__device__ void block_sum3(float &S, float &Sx, float &Sy) {
    __shared__ float ss[NW][3];
    int tid = threadIdx.x;
    __syncthreads();                       // protect smem reuse across calls
    #pragma unroll
    for (int o = 16; o; o >>= 1) {
        S  += __shfl_xor_sync(0xffffffffu, S, o);
        Sx += __shfl_xor_sync(0xffffffffu, Sx, o);
        Sy += __shfl_xor_sync(0xffffffffu, Sy, o);
    }
    if ((tid & 31) == 0) { ss[tid >> 5][0] = S; ss[tid >> 5][1] = Sx; ss[tid >> 5][2] = Sy; }
    __syncthreads();
    if (tid < 32) {
        S = ss[tid][0]; Sx = ss[tid][1]; Sy = ss[tid][2];
        #pragma unroll
        for (int o = 16; o; o >>= 1) {
            S  += __shfl_xor_sync(0xffffffffu, S, o);
            Sx += __shfl_xor_sync(0xffffffffu, Sx, o);
            Sy += __shfl_xor_sync(0xffffffffu, Sy, o);
        }
    }
}

// Fixed-max accumulate (phase0 reload). Ms is the SCALED (x100) block max.
__device__ __forceinline__ void accf(float Ms, float &S, float &Sx, float &Sy,
                                     float raw, float x, float y) {
    float v = raw * 100.f;
    if (v > Ms - 88.f) {
        float e = expf(v - Ms);
        S += e; Sx += x * e; Sy += y * e;
    }
}

__global__ void __launch_bounds__(NT, 1)
sa_kernel(const float * __restrict__ hm, float * __restrict__ out) {
    const int b = blockIdx.x;
    const int tid = threadIdx.x;
    __shared__ unsigned s_base;
    __shared__ float s_ay, s_ay2[2];
    __shared__ float sMp[16], sSp[16], sSxp[16], sSyp[16];

    if (tid == 0) s_base = ld_acq(&g_flag[b]);   // own flag: +EPT per launch, stable base
    __syncthreads();
    const unsigned base = s_base;

    const int c  = (b < CBLK) ? 0 : 1;
    const int bb = (b < CBLK) ? b : b - CBLK;
    const float4 *p4 = reinterpret_cast<const float4*>(hm + (size_t)(9 + c) * HH * WW);
    const int ibase = bb * NT + tid;

    // ======== Phase 0 (single pass): block-max-relative sums, merged later ========
    {
        // pass A: branch-free RAW max, tile maxima kept in regs
        float bmx[4];
        #pragma unroll
        for (int k = 0; k < 3; k++) {
            float4 A = p4[ibase + (4*k + 0) * STR];
            float4 B = p4[ibase + (4*k + 1) * STR];
            float4 C = p4[ibase + (4*k + 2) * STR];
            float4 D = p4[ibase + (4*k + 3) * STR];
            bmx[k] = fmaxf(fmaxf(fmax4(A), fmax4(B)), fmaxf(fmax4(C), fmax4(D)));
        }
        {
            float4 A = p4[ibase + 12 * STR];
            float m3 = fmax4(A);
            int i13 = ibase + 13 * STR;
            if (i13 < TOT4) { float4 B = p4[i13]; m3 = fmaxf(m3, fmax4(B)); }
            bmx[3] = m3;
        }
        float Mb = block_max_bcast(fmaxf(fmaxf(bmx[0], bmx[1]), fmaxf(bmx[2], bmx[3])));

        // pass B: ballot-skip reload of qualifying tiles (L1/L2 hits), sums rel. block max
        const float Ms     = Mb * 100.f;
        const float thrRaw = Mb - 0.88f;
        float S = 0.f, Sx = 0.f, Sy = 0.f;
        #pragma unroll
        for (int k = 0; k < 4; k++) {
            if (__any_sync(0xffffffffu, bmx[k] > thrRaw)) {
                int tlo = 4 * k, thi = (k == 3) ? 14 : 4 * k + 4;
                for (int t = tlo; t < thi; t++) {
                    int idx = ibase + t * STR;
                    if (idx < TOT4) {
                        float4 A = p4[idx];
                        float y  = (float)(idx >> 9);
                        float x0 = (float)((idx & 511) << 2);
                        accf(Ms, S, Sx, Sy, A.x, x0,       y);
                        accf(Ms, S, Sx, Sy, A.y, x0 + 1.f, y);
                        accf(Ms, S, Sx, Sy, A.z, x0 + 2.f, y);
                        accf(Ms, S, Sx, Sy, A.w, x0 + 3.f, y);
                    }
                }
            }
        }
        block_sum3(S, Sx, Sy);
        if (tid == 0) {
            g_part[2][b] = make_float4(Mb, S, Sx, Sy);   // RAW max + relative sums
            st_rel(&g_flag[b], (b >= SUB) ? base + EPT : base + 1);
        }
    }
    if (b >= SUB) return;                     // 116 blocks done

    // wait for all 148 phase-0 partials (backoff poll; acquire pairs with releases)
    if (tid < NB) {
        while (ld_acq(&g_flag[tid]) < base + 1) __nanosleep(64);
    }
    __syncthreads();

    // ---- Phase 0 finisher: two-step logsumexp merge of 74 partials per channel ----
    for (int cc = 0; cc < 2; cc++) {
        float Mk = neg_inf(), S = 0.f, Sx = 0.f, Sy = 0.f;
        if (tid < CBLK) {
            float4 p = g_part[2][cc * CBLK + tid];
            Mk = p.x; S = p.y; Sx = p.z; Sy = p.w;
        }
        float Mg = block_max_bcast(Mk);
        float e = (tid < CBLK) ? expf((Mk - Mg) * 100.f) : 0.f;
        S *= e; Sx *= e; Sy *= e;
        block_sum3(S, Sx, Sy);
        if (tid == 0) {
            float ax = Sx / S, ay = Sy / S;
            s_ay2[cc] = ay;
            if (b == 0) { out[(9 + cc) * 2 + 0] = ax; out[(9 + cc) * 2 + 1] = ay; }
        }
        __syncthreads();
    }
    // per-thread serial state (identical in every thread of every subgroup block)
    float yA = s_ay2[0], yB = s_ay2[1];
    float dis = __fsub_rn(yB, yA), dsum = 0.f, dnum = 0.f;

    // ================= Band phases i = 8 .. 0 (2 BARs + 1 release hop each) =================
    for (int i = 8; i >= 0; i--) {
        // scalar band logic, computed redundantly by ALL threads;
        // __f*_rn blocks FMA contraction to match reference
        {
            float tmp = ceilf(__fsub_rn(yB, yA));
            if (fabsf(__fsub_rn(tmp, dis)) > __fmul_rn(0.35f, dis)) {
                dsum = __fadd_rn(dsum, tmp);
                dnum = __fadd_rn(dnum, 1.0f);
                dis  = __fdiv_rn(dsum, fmaxf(dnum, 1.0f));
            }
        }
        float last_y = floorf(yA);
        float t  = __fmul_rn(1.8f, dis);
        float sr = __fsub_rn(last_y, t);
        float end_y   = rintf(__fadd_rn(sr, t));   // round-half-even = jnp.round
        float start_y = rintf(sr);
        const int r0 = (start_y <= 0.f) ? 0  : (start_y >= (float)HH       ? HH     : (int)start_y);
        const int r1 = (end_y   <  0.f) ? -1 : (end_y   >= (float)(HH - 1) ? HH - 1 : (int)end_y);
        const int rows = r1 - r0 + 1;

        const int j  = 8 - i;
        const int bi = j & 1;                       // double-buffer by band parity
        const unsigned ptag = base + 2 + (unsigned)j;   // 2..10 < EPT

        if (rows <= SUB) {
            // ---- fast path: one row per block, per-warp partials, 2 BARs total ----
            const int w = tid >> 5;
            float Mw = neg_inf(), S = 0.f, Sx = 0.f, Sy = 0.f;
            if (w < 16 && b < rows) {
                const int row = r0 + b;
                const float4 *rp = reinterpret_cast<const float4*>(hm + ((size_t)i * HH + row) * WW);
                float4 A = rp[tid];
                float v0 = A.x * 100.f, v1 = A.y * 100.f, v2 = A.z * 100.f, v3 = A.w * 100.f;
                float wm = fmaxf(fmaxf(v0, v1), fmaxf(v2, v3));
                #pragma unroll
                for (int o = 16; o; o >>= 1) wm = fmaxf(wm, __shfl_xor_sync(0xffffffffu, wm, o));
                float e0 = expf(v0 - wm), e1 = expf(v1 - wm), e2 = expf(v2 - wm), e3 = expf(v3 - wm);
                float es = (e0 + e1) + (e2 + e3);
                float x0 = (float)(tid << 2);
                S  = es;
                Sx = x0 * e0 + (x0 + 1.f) * e1 + (x0 + 2.f) * e2 + (x0 + 3.f) * e3;
                Sy = (float)row * es;
                #pragma unroll
                for (int o = 16; o; o >>= 1) {
                    S  += __shfl_xor_sync(0xffffffffu, S, o);
                    Sx += __shfl_xor_sync(0xffffffffu, Sx, o);
                    Sy += __shfl_xor_sync(0xffffffffu, Sy, o);
                }
                Mw = wm;
            }
            if ((tid & 31) == 0 && w < 16) { sMp[w] = Mw; sSp[w] = S; sSxp[w] = Sx; sSyp[w] = Sy; }
            __syncthreads();                    // BAR A
            if (tid < 32) {
                // fold 16 warp partials (two-step) -> block partial, publish
                float Mk = (tid < 16) ? sMp[tid] : neg_inf();
                float S2 = (tid < 16) ? sSp[tid] : 0.f;
                float Sx2 = (tid < 16) ? sSxp[tid] : 0.f;
                float Sy2 = (tid < 16) ? sSyp[tid] : 0.f;
                float Mb = Mk;
                #pragma unroll
                for (int o = 16; o; o >>= 1) Mb = fmaxf(Mb, __shfl_xor_sync(0xffffffffu, Mb, o));
                float e = (Mk == neg_inf()) ? 0.f : expf(Mk - Mb);
                S2 *= e; Sx2 *= e; Sy2 *= e;
                #pragma unroll
                for (int o = 16; o; o >>= 1) {
                    S2  += __shfl_xor_sync(0xffffffffu, S2, o);
                    Sx2 += __shfl_xor_sync(0xffffffffu, Sx2, o);
                    Sy2 += __shfl_xor_sync(0xffffffffu, Sy2, o);
                }
                if (tid == 0) {
                    g_part[bi][b] = make_float4(Mb, S2, Sx2, Sy2);
                    st_rel(&g_flag[b], ptag);
                }
                // gather the 32 block partials (acquire poll; data follows)
                while (ld_acq(&g_flag[tid]) < ptag) {}
                float4 p = g_part[bi][tid];
                float Mk2 = p.x, T = p.y, Tx = p.z, Ty = p.w;
                float Mg = Mk2;
                #pragma unroll
                for (int o = 16; o; o >>= 1) Mg = fmaxf(Mg, __shfl_xor_sync(0xffffffffu, Mg, o));
                float e2 = (Mk2 == neg_inf()) ? 0.f : expf(Mk2 - Mg);
                T *= e2; Tx *= e2; Ty *= e2;
                #pragma unroll
                for (int o = 16; o; o >>= 1) {
                    T  += __shfl_xor_sync(0xffffffffu, T, o);
                    Tx += __shfl_xor_sync(0xffffffffu, Tx, o);
                    Ty += __shfl_xor_sync(0xffffffffu, Ty, o);
                }
                if (tid == 0) {
                    float Rn = (rows > 0) ? (float)rows : 0.f;
                    float m;
                    if (Rn >= 2048.f)      m = Mg;
                    else if (Rn > 0.f)     m = fmaxf(Mg, 0.f);
                    else                   m = 0.f;
                    float sc = (Rn > 0.f) ? expf(Mg - m) : 0.f;
                    T *= sc; Tx *= sc; Ty *= sc;
                    if (Rn < 2048.f) {
                        const float NTOT  = 4194304.f;      // H*W
                        const float SXROW = 2096128.f;      // W*(W-1)/2
                        const float SXTOT = 4292870144.f;   // H * SXROW
                        const float SYTOT = 4292870144.f;   // W * H*(H-1)/2
                        float e0 = expf(-m);
                        T  += (NTOT  - Rn * 2048.f) * e0;
                        Tx += (SXTOT - Rn * SXROW ) * e0;
                        Ty += (SYTOT - 2048.f * (0.5f * (float)(r0 + r1) * Rn)) * e0;
                    }
                    float ax = Tx / T, ay = Ty / T;
                    s_ay = ay;
                    if (b == 0) { out[i * 2 + 0] = ax; out[i * 2 + 1] = ay; }
                }
            }
            __syncthreads();                    // BAR B
        } else {
            // ---- slow path (wide band, rare): block-wide online + same publish/gather ----
            float Mt = neg_inf(), S = 0.f, Sx = 0.f, Sy = 0.f;
            if (tid < 512) {
                const float x0 = (float)(tid << 2);
                for (int row = r0 + b; row <= r1; row += SUB) {
                    const float4 *rp = reinterpret_cast<const float4*>(hm + ((size_t)i * HH + row) * WW);
                    float4 A = rp[tid];
                    float v0 = A.x * 100.f, v1 = A.y * 100.f, v2 = A.z * 100.f, v3 = A.w * 100.f;
                    float mr = fmaxf(fmaxf(v0, v1), fmaxf(v2, v3));
                    if (mr > Mt) {
                        float r = expf(Mt - mr);   // expf(-inf)=0 on first row
                        S *= r; Sx *= r; Sy *= r;
                        Mt = mr;
                    }
                    float e0 = expf(v0 - Mt), e1 = expf(v1 - Mt), e2 = expf(v2 - Mt), e3 = expf(v3 - Mt);
                    float es = (e0 + e1) + (e2 + e3);
                    S  += es;
                    Sx += x0 * e0 + (x0 + 1.f) * e1 + (x0 + 2.f) * e2 + (x0 + 3.f) * e3;
                    Sy += (float)row * es;
                }
            }
            float Mb = block_max_bcast(Mt);
            float e = (Mt == neg_inf()) ? 0.f : expf(Mt - Mb);
            S *= e; Sx *= e; Sy *= e;
            block_sum3(S, Sx, Sy);
            if (tid < 32) {
                if (tid == 0) {
                    g_part[bi][b] = make_float4((S == 0.f && Mt == neg_inf() && Mb == neg_inf()) ? neg_inf() : Mb, S, Sx, Sy);
                    st_rel(&g_flag[b], ptag);
                }
                while (ld_acq(&g_flag[tid]) < ptag) {}
                float4 p = g_part[bi][tid];
                float Mk2 = p.x, T = p.y, Tx = p.z, Ty = p.w;
                float Mg = Mk2;
                #pragma unroll
                for (int o = 16; o; o >>= 1) Mg = fmaxf(Mg, __shfl_xor_sync(0xffffffffu, Mg, o));
                float e2 = (Mk2 == neg_inf()) ? 0.f : expf(Mk2 - Mg);
                T *= e2; Tx *= e2; Ty *= e2;
                #pragma unroll
                for (int o = 16; o; o >>= 1) {
                    T  += __shfl_xor_sync(0xffffffffu, T, o);
                    Tx += __shfl_xor_sync(0xffffffffu, Tx, o);
                    Ty += __shfl_xor_sync(0xffffffffu, Ty, o);
                }
                if (tid == 0) {
                    float Rn = (float)rows;
                    float m = (Rn >= 2048.f) ? Mg : fmaxf(Mg, 0.f);
                    float sc = expf(Mg - m);
                    T *= sc; Tx *= sc; Ty *= sc;
                    if (Rn < 2048.f) {
                        const float NTOT  = 4194304.f;
                        const float SXROW = 2096128.f;
                        const float SXTOT = 4292870144.f;
                        const float SYTOT = 4292870144.f;
                        float e0 = expf(-m);
                        T  += (NTOT  - Rn * 2048.f) * e0;
                        Tx += (SXTOT - Rn * SXROW ) * e0;
                        Ty += (SYTOT - 2048.f * (0.5f * (float)(r0 + r1) * Rn)) * e0;
                    }
                    float ax = Tx / T, ay = Ty / T;
                    s_ay = ay;
                    if (b == 0) { out[i * 2 + 0] = ax; out[i * 2 + 1] = ay; }
                }
            }
            __syncthreads();
        }
        yB = yA;
        yA = s_ay;
    }

    // restore the uniform +EPT-per-launch flag invariant
    if (tid == 0) st_rel(&g_flag[b], base + EPT);
}

extern "C" void kernel_launch(void* const* d_in, const int* in_sizes, int n_in,
                              void* d_out, int out_size) {
    const float *hm = (const float*)d_in[0];
    float *out = (float*)d_out;
    (void)in_sizes; (void)n_in; (void)out_size;

    sa_kernel<<<NB, NT>>>(hm, out);
}

// round 11
// speedup vs baseline: 1.3326x; 1.3326x over previous
#include <cuda_runtime.h>

#define HH 2048
#define WW 2048
#define NB 148
#define NT 1024
#define NW 32
#define CBLK 74
#define TOT4 (HH*WW/4)          // 1,048,576 float4 per channel
#define STR (CBLK*NT)           // 75,776
#define SUB 32                  // band subgroup size
#define EPT 12                  // flag increment per launch for kernel B (epochs used: 1..9)

// Scratch (device globals; no allocation allowed)
// slots 0,1: band double-buffer (first SUB entries); 2: phase0 block-relative partials
__device__ float4 g_part[3][NB];
__device__ unsigned g_flag[SUB];         // kernel-B per-block monotone epoch flags

__device__ __forceinline__ float neg_inf() { return __int_as_float(0xff800000); }
__device__ __forceinline__ float fmax4(float4 A) {
    return fmaxf(fmaxf(A.x, A.y), fmaxf(A.z, A.w));
}

// Block-wide max, broadcast to ALL threads.
__device__ float block_max_bcast(float m) {
    __shared__ float sm[NW];
    __shared__ float sM;
    int tid = threadIdx.x;
    __syncthreads();                       // protect smem reuse across calls
    #pragma unroll
    for (int o = 16; o; o >>= 1) m = fmaxf(m, __shfl_xor_sync(0xffffffffu, m, o));
    if ((tid & 31) == 0) sm[tid >> 5] = m;
    __syncthreads();
    if (tid < 32) {
        float t = sm[tid];
        #pragma unroll
        for (int o = 16; o; o >>= 1) t = fmaxf(t, __shfl_xor_sync(0xffffffffu, t, o));
        if (tid == 0) sM = t;
    }
    __syncthreads();
    return sM;
}

// Block-wide 3-way sum; result valid on threads 0..31.
__device__ void block_sum3(float &S, float &Sx, float &Sy) {
    __shared__ float ss[NW][3];
    int tid = threadIdx.x;
    __syncthreads();                       // protect smem reuse across calls
    #pragma unroll
    for (int o = 16; o; o >>= 1) {
        S  += __shfl_xor_sync(0xffffffffu, S, o);
        Sx += __shfl_xor_sync(0xffffffffu, Sx, o);
        Sy += __shfl_xor_sync(0xffffffffu, Sy, o);
    }
    if ((tid & 31) == 0) { ss[tid >> 5][0] = S; ss[tid >> 5][1] = Sx; ss[tid >> 5][2] = Sy; }
    __syncthreads();
    if (tid < 32) {
        S = ss[tid][0]; Sx = ss[tid][1]; Sy = ss[tid][2];
        #pragma unroll
        for (int o = 16; o; o >>= 1) {
            S  += __shfl_xor_sync(0xffffffffu, S, o);
            Sx += __shfl_xor_sync(0xffffffffu, Sx, o);
            Sy += __shfl_xor_sync(0xffffffffu, Sy, o);
        }
    }
}

// Fixed-max accumulate (phase0 reload). Ms is the SCALED (x100) block max.
__device__ __forceinline__ void accf(float Ms, float &S, float &Sx, float &Sy,
                                     float raw, float x, float y) {
    float v = raw * 100.f;
    if (v > Ms - 88.f) {
        float e = expf(v - Ms);
        S += e; Sx += x * e; Sy += y * e;
    }
}

__device__ __forceinline__ void flag_set(int b, unsigned v) {
    *(volatile unsigned*)&g_flag[b] = v;
}
__device__ __forceinline__ void flag_wait(int n, unsigned target) {
    int tid = threadIdx.x;
    if (tid < n) {
        while (*(volatile unsigned*)&g_flag[tid] < target) {}
    }
    __syncthreads();
    __threadfence();
}

// ================= Kernel A: phase-0 streaming (no barriers, no flags) =================
__global__ void __launch_bounds__(NT, 1)
phase0_kernel(const float * __restrict__ hm) {
    const int b = blockIdx.x;
    const int tid = threadIdx.x;
    const int c  = (b < CBLK) ? 0 : 1;
    const int bb = (b < CBLK) ? b : b - CBLK;
    const float4 *p4 = reinterpret_cast<const float4*>(hm + (size_t)(9 + c) * HH * WW);
    const int ibase = bb * NT + tid;

    // pass A: branch-free RAW max, tile maxima kept in regs
    float bmx[4];
    #pragma unroll
    for (int k = 0; k < 3; k++) {
        float4 A = p4[ibase + (4*k + 0) * STR];
        float4 B = p4[ibase + (4*k + 1) * STR];
        float4 C = p4[ibase + (4*k + 2) * STR];
        float4 D = p4[ibase + (4*k + 3) * STR];
        bmx[k] = fmaxf(fmaxf(fmax4(A), fmax4(B)), fmaxf(fmax4(C), fmax4(D)));
    }
    {
        float4 A = p4[ibase + 12 * STR];
        float m3 = fmax4(A);
        int i13 = ibase + 13 * STR;
        if (i13 < TOT4) { float4 B = p4[i13]; m3 = fmaxf(m3, fmax4(B)); }
        bmx[3] = m3;
    }
    float Mb = block_max_bcast(fmaxf(fmaxf(bmx[0], bmx[1]), fmaxf(bmx[2], bmx[3])));

    // pass B: ballot-skip reload of qualifying tiles (L2 hits), sums rel. BLOCK max
    const float Ms     = Mb * 100.f;
    const float thrRaw = Mb - 0.88f;
    float S = 0.f, Sx = 0.f, Sy = 0.f;
    #pragma unroll
    for (int k = 0; k < 4; k++) {
        if (__any_sync(0xffffffffu, bmx[k] > thrRaw)) {
            int tlo = 4 * k, thi = (k == 3) ? 14 : 4 * k + 4;
            for (int t = tlo; t < thi; t++) {
                int idx = ibase + t * STR;
                if (idx < TOT4) {
                    float4 A = p4[idx];
                    float y  = (float)(idx >> 9);
                    float x0 = (float)((idx & 511) << 2);
                    accf(Ms, S, Sx, Sy, A.x, x0,       y);
                    accf(Ms, S, Sx, Sy, A.y, x0 + 1.f, y);
                    accf(Ms, S, Sx, Sy, A.z, x0 + 2.f, y);
                    accf(Ms, S, Sx, Sy, A.w, x0 + 3.f, y);
                }
            }
        }
    }
    block_sum3(S, Sx, Sy);
    if (tid == 0) g_part[2][b] = make_float4(Mb, S, Sx, Sy);   // RAW max + relative sums
}

// ================= Kernel B: finisher + 9 serial band phases (32 blocks) =================
__global__ void __launch_bounds__(NT, 1)
bands_kernel(const float * __restrict__ hm, float * __restrict__ out) {
    const int b = blockIdx.x;
    const int tid = threadIdx.x;
    __shared__ unsigned s_base;
    __shared__ float s_ay, s_ay2[2];
    __shared__ float sMp[SUB], sSp[SUB], sSxp[SUB], sSyp[SUB];

    if (tid == 0) s_base = *(volatile unsigned*)&g_flag[b];
    __syncthreads();
    const unsigned base = s_base;

    // ---- Phase 0 finisher: two-step logsumexp merge of 74 partials per channel ----
    for (int cc = 0; cc < 2; cc++) {
        float Mk = neg_inf(), S = 0.f, Sx = 0.f, Sy = 0.f;
        if (tid < CBLK) {
            float4 p = g_part[2][cc * CBLK + tid];
            Mk = p.x; S = p.y; Sx = p.z; Sy = p.w;
        }
        float Mg = block_max_bcast(Mk);
        float e = (tid < CBLK) ? expf((Mk - Mg) * 100.f) : 0.f;
        S *= e; Sx *= e; Sy *= e;
        block_sum3(S, Sx, Sy);
        if (tid == 0) {
            float ax = Sx / S, ay = Sy / S;
            s_ay2[cc] = ay;
            if (b == 0) { out[(9 + cc) * 2 + 0] = ax; out[(9 + cc) * 2 + 1] = ay; }
        }
        __syncthreads();
    }
    float yA = s_ay2[0], yB = s_ay2[1];
    float dis = __fsub_rn(yB, yA), dsum = 0.f, dnum = 0.f;

    // ---------------- Band phases i = 8 .. 0 (R9-proven protocol) ----------------
    for (int i = 8; i >= 0; i--) {
        // scalar band logic, computed redundantly by ALL threads;
        // __f*_rn blocks FMA contraction to match reference
        {
            float tmp = ceilf(__fsub_rn(yB, yA));
            if (fabsf(__fsub_rn(tmp, dis)) > __fmul_rn(0.35f, dis)) {
                dsum = __fadd_rn(dsum, tmp);
                dnum = __fadd_rn(dnum, 1.0f);
                dis  = __fdiv_rn(dsum, fmaxf(dnum, 1.0f));
            }
        }
        float last_y = floorf(yA);
        float t  = __fmul_rn(1.8f, dis);
        float sr = __fsub_rn(last_y, t);
        float end_y   = rintf(__fadd_rn(sr, t));   // round-half-even = jnp.round
        float start_y = rintf(sr);
        const int r0 = (start_y <= 0.f) ? 0  : (start_y >= (float)HH       ? HH     : (int)start_y);
        const int r1 = (end_y   <  0.f) ? -1 : (end_y   >= (float)(HH - 1) ? HH - 1 : (int)end_y);
        const int rows = r1 - r0 + 1;

        const int j  = 8 - i;
        const int bi = j & 1;                       // double-buffer by band parity
        const unsigned ptag = base + 1 + (unsigned)j;   // 1..9 < EPT

        float Mloc = neg_inf(), S = 0.f, Sx = 0.f, Sy = 0.f;
        if (rows <= SUB) {
            // ---- fast path: one row per block; two-step max -> conditional exp ----
            int row = r0 + b;
            bool act = (tid < 512) && (b < rows);
            float v0 = 0.f, v1 = 0.f, v2 = 0.f, v3 = 0.f, mt = neg_inf();
            if (act) {
                const float4 *rp = reinterpret_cast<const float4*>(hm + ((size_t)i * HH + row) * WW);
                float4 A = rp[tid];
                v0 = A.x * 100.f; v1 = A.y * 100.f; v2 = A.z * 100.f; v3 = A.w * 100.f;
                mt = fmaxf(fmaxf(v0, v1), fmaxf(v2, v3));
            }
            float Mb = block_max_bcast(mt);     // this block's row max (scaled)
            Mloc = Mb;
            if (__any_sync(0xffffffffu, mt > Mb - 88.f)) {
                if (act) {
                    float e0 = expf(v0 - Mb), e1 = expf(v1 - Mb);
                    float e2 = expf(v2 - Mb), e3 = expf(v3 - Mb);
                    float es = (e0 + e1) + (e2 + e3);
                    float x0 = (float)(tid << 2);
                    S  += es;
                    Sx += x0 * e0 + (x0 + 1.f) * e1 + (x0 + 2.f) * e2 + (x0 + 3.f) * e3;
                    Sy += (float)row * es;
                }
            }
            block_sum3(S, Sx, Sy);
        } else {
            // ---- slow path (wide band): online rescale per row ----
            float Mt = neg_inf();
            if (tid < 512) {
                const float x0 = (float)(tid << 2);
                for (int row = r0 + b; row <= r1; row += SUB) {
                    const float4 *rp = reinterpret_cast<const float4*>(hm + ((size_t)i * HH + row) * WW);
                    float4 A = rp[tid];
                    float v0 = A.x * 100.f, v1 = A.y * 100.f, v2 = A.z * 100.f, v3 = A.w * 100.f;
                    float mr = fmaxf(fmaxf(v0, v1), fmaxf(v2, v3));
                    if (mr > Mt) {
                        float r = expf(Mt - mr);   // expf(-inf)=0 on first row
                        S *= r; Sx *= r; Sy *= r;
                        Mt = mr;
                    }
                    float e0 = expf(v0 - Mt), e1 = expf(v1 - Mt), e2 = expf(v2 - Mt), e3 = expf(v3 - Mt);
                    float es = (e0 + e1) + (e2 + e3);
                    S  += es;
                    Sx += x0 * e0 + (x0 + 1.f) * e1 + (x0 + 2.f) * e2 + (x0 + 3.f) * e3;
                    Sy += (float)row * es;
                }
            }
            float Mb = block_max_bcast(Mt);
            float e = (Mt == neg_inf()) ? 0.f : expf(Mt - Mb);
            S *= e; Sx *= e; Sy *= e;
            Mloc = Mb;
            block_sum3(S, Sx, Sy);
        }
        if (tid == 0) {
            g_part[bi][b] = make_float4(Mloc, S, Sx, Sy);
            __threadfence();
            flag_set(b, ptag);
        }
        flag_wait(SUB, ptag);               // mini-barrier among 32 blocks

        // stage the 32 partials into smem, then single-warp finisher + closed-form tail
        if (tid < SUB) {
            float4 p = g_part[bi][tid];
            sMp[tid] = p.x; sSp[tid] = p.y; sSxp[tid] = p.z; sSyp[tid] = p.w;
        }
        __syncthreads();
        if (tid < 32) {
            float Mk = sMp[tid], S2 = sSp[tid], Sx2 = sSxp[tid], Sy2 = sSyp[tid];
            float Mb = Mk;
            #pragma unroll
            for (int o = 16; o; o >>= 1) Mb = fmaxf(Mb, __shfl_xor_sync(0xffffffffu, Mb, o));
            float e = (Mk == neg_inf()) ? 0.f : expf(Mk - Mb);
            S2 *= e; Sx2 *= e; Sy2 *= e;
            #pragma unroll
            for (int o = 16; o; o >>= 1) {
                S2  += __shfl_xor_sync(0xffffffffu, S2, o);
                Sx2 += __shfl_xor_sync(0xffffffffu, Sx2, o);
                Sy2 += __shfl_xor_sync(0xffffffffu, Sy2, o);
            }
            if (tid == 0) {
                float Rn = (rows > 0) ? (float)rows : 0.f;
                float m;
                if (Rn >= 2048.f)      m = Mb;               // band covers everything
                else if (Rn > 0.f)     m = fmaxf(Mb, 0.f);   // zeros exist outside band
                else                   m = 0.f;              // empty band: all-zero map
                float sc = (Rn > 0.f) ? expf(Mb - m) : 0.f;
                S2 *= sc; Sx2 *= sc; Sy2 *= sc;
                if (Rn < 2048.f) {
                    const float NTOT  = 4194304.f;      // H*W
                    const float SXROW = 2096128.f;      // W*(W-1)/2
                    const float SXTOT = 4292870144.f;   // H * SXROW
                    const float SYTOT = 4292870144.f;   // W * H*(H-1)/2
                    float e0 = expf(-m);
                    S2  += (NTOT  - Rn * 2048.f) * e0;
                    Sx2 += (SXTOT - Rn * SXROW ) * e0;
                    Sy2 += (SYTOT - 2048.f * (0.5f * (float)(r0 + r1) * Rn)) * e0;
                }
                float ax = Sx2 / S2, ay = Sy2 / S2;
                s_ay = ay;
                if (b == 0) { out[i * 2 + 0] = ax; out[i * 2 + 1] = ay; }
            }
        }
        __syncthreads();
        yB = yA;
        yA = s_ay;
    }

    // restore the uniform +EPT-per-launch flag invariant
    if (tid == 0) flag_set(b, base + EPT);
}

extern "C" void kernel_launch(void* const* d_in, const int* in_sizes, int n_in,
                              void* d_out, int out_size) {
    const float *hm = (const float*)d_in[0];
    float *out = (float*)d_out;
    (void)in_sizes; (void)n_in; (void)out_size;

    phase0_kernel<<<NB, NT>>>(hm);
    bands_kernel<<<SUB, NT>>>(hm, out);
}

// round 12
// speedup vs baseline: 1.7929x; 1.3454x over previous
#include <cuda_runtime.h>
#include <cstdint>

#define HH 2048
#define WW 2048
#define NB 148
#define NT 1024
#define NW 32
#define CBLK 74
#define TOT4 (HH*WW/4)          // 1,048,576 float4 per channel
#define STR (CBLK*NT)           // 75,776
#define CSZ 8                   // band cluster size

// Only cross-kernel state: phase-0 block partials, fully rewritten each launch.
__device__ float4 g_p0[NB];

__device__ __forceinline__ float neg_inf() { return __int_as_float(0xff800000); }
__device__ __forceinline__ float fmax4(float4 A) {
    return fmaxf(fmaxf(A.x, A.y), fmaxf(A.z, A.w));
}

// ---- DSMEM helpers ----
__device__ __forceinline__ uint32_t smem_u32(const void *p) {
    return (uint32_t)__cvta_generic_to_shared(p);
}
__device__ __forceinline__ uint32_t mapa_u32(uint32_t a, uint32_t rank) {
    uint32_t r;
    asm volatile("mapa.shared::cluster.u32 %0, %1, %2;" : "=r"(r) : "r"(a), "r"(rank));
    return r;
}
__device__ __forceinline__ float ld_clu_f32(uint32_t a) {
    uint32_t v;
    asm volatile("ld.shared::cluster.b32 %0, [%1];" : "=r"(v) : "r"(a) : "memory");
    return __uint_as_float(v);
}
#define CLUSTER_BAR() do { \
    asm volatile("barrier.cluster.arrive.aligned;" ::: "memory"); \
    asm volatile("barrier.cluster.wait.aligned;"   ::: "memory"); \
} while (0)

// Block-wide max, broadcast to ALL threads (3 bars; used outside band loop).
__device__ float block_max_bcast(float m) {
    __shared__ float sm[NW];
    __shared__ float sM;
    int tid = threadIdx.x;
    __syncthreads();
    #pragma unroll
    for (int o = 16; o; o >>= 1) m = fmaxf(m, __shfl_xor_sync(0xffffffffu, m, o));
    if ((tid & 31) == 0) sm[tid >> 5] = m;
    __syncthreads();
    if (tid < 32) {
        float t = sm[tid];
        #pragma unroll
        for (int o = 16; o; o >>= 1) t = fmaxf(t, __shfl_xor_sync(0xffffffffu, t, o));
        if (tid == 0) sM = t;
    }
    __syncthreads();
    return sM;
}

// Block-wide 3-way sum; result valid on threads 0..31.
__device__ void block_sum3(float &S, float &Sx, float &Sy) {
    __shared__ float ss[NW][3];
    int tid = threadIdx.x;
    __syncthreads();
    #pragma unroll
    for (int o = 16; o; o >>= 1) {
        S  += __shfl_xor_sync(0xffffffffu, S, o);
        Sx += __shfl_xor_sync(0xffffffffu, Sx, o);
        Sy += __shfl_xor_sync(0xffffffffu, Sy, o);
    }
    if ((tid & 31) == 0) { ss[tid >> 5][0] = S; ss[tid >> 5][1] = Sx; ss[tid >> 5][2] = Sy; }
    __syncthreads();
    if (tid < 32) {
        S = ss[tid][0]; Sx = ss[tid][1]; Sy = ss[tid][2];
        #pragma unroll
        for (int o = 16; o; o >>= 1) {
            S  += __shfl_xor_sync(0xffffffffu, S, o);
            Sx += __shfl_xor_sync(0xffffffffu, Sx, o);
            Sy += __shfl_xor_sync(0xffffffffu, Sy, o);
        }
    }
}

// Fixed-max accumulate (phase0 reload). Ms is the SCALED (x100) block max.
__device__ __forceinline__ void accf(float Ms, float &S, float &Sx, float &Sy,
                                     float raw, float x, float y) {
    float v = raw * 100.f;
    if (v > Ms - 88.f) {
        float e = expf(v - Ms);
        S += e; Sx += x * e; Sy += y * e;
    }
}

// ================= Kernel A: phase-0 streaming (148 blocks, no sync) =================
__global__ void __launch_bounds__(NT, 1)
phase0_kernel(const float * __restrict__ hm) {
    const int b = blockIdx.x;
    const int tid = threadIdx.x;
    const int c  = (b < CBLK) ? 0 : 1;
    const int bb = (b < CBLK) ? b : b - CBLK;
    const float4 *p4 = reinterpret_cast<const float4*>(hm + (size_t)(9 + c) * HH * WW);
    const int ibase = bb * NT + tid;

    // pass A: branch-free RAW max, tile maxima kept in regs
    float bmx[4];
    #pragma unroll
    for (int k = 0; k < 3; k++) {
        float4 A = p4[ibase + (4*k + 0) * STR];
        float4 B = p4[ibase + (4*k + 1) * STR];
        float4 C = p4[ibase + (4*k + 2) * STR];
        float4 D = p4[ibase + (4*k + 3) * STR];
        bmx[k] = fmaxf(fmaxf(fmax4(A), fmax4(B)), fmaxf(fmax4(C), fmax4(D)));
    }
    {
        float4 A = p4[ibase + 12 * STR];
        float m3 = fmax4(A);
        int i13 = ibase + 13 * STR;
        if (i13 < TOT4) { float4 B = p4[i13]; m3 = fmaxf(m3, fmax4(B)); }
        bmx[3] = m3;
    }
    float Mb = block_max_bcast(fmaxf(fmaxf(bmx[0], bmx[1]), fmaxf(bmx[2], bmx[3])));

    // pass B: ballot-skip reload of qualifying tiles (L2 hits), sums rel. BLOCK max
    const float Ms     = Mb * 100.f;
    const float thrRaw = Mb - 0.88f;
    float S = 0.f, Sx = 0.f, Sy = 0.f;
    #pragma unroll
    for (int k = 0; k < 4; k++) {
        if (__any_sync(0xffffffffu, bmx[k] > thrRaw)) {
            int tlo = 4 * k, thi = (k == 3) ? 14 : 4 * k + 4;
            for (int t = tlo; t < thi; t++) {
                int idx = ibase + t * STR;
                if (idx < TOT4) {
                    float4 A = p4[idx];
                    float y  = (float)(idx >> 9);
                    float x0 = (float)((idx & 511) << 2);
                    accf(Ms, S, Sx, Sy, A.x, x0,       y);
                    accf(Ms, S, Sx, Sy, A.y, x0 + 1.f, y);
                    accf(Ms, S, Sx, Sy, A.z, x0 + 2.f, y);
                    accf(Ms, S, Sx, Sy, A.w, x0 + 3.f, y);
                }
            }
        }
    }
    block_sum3(S, Sx, Sy);
    if (tid == 0) g_p0[b] = make_float4(Mb, S, Sx, Sy);   // RAW max + relative sums
}

// 2-bar CTA max broadcast (dedicated smem, safe without entry sync in the band loop)
__device__ __forceinline__ float cmax2(float m) {
    __shared__ float sWm[NW];
    __shared__ float sMx;
    int tid = threadIdx.x;
    #pragma unroll
    for (int o = 16; o; o >>= 1) m = fmaxf(m, __shfl_xor_sync(0xffffffffu, m, o));
    if ((tid & 31) == 0) sWm[tid >> 5] = m;
    __syncthreads();
    if (tid < 32) {
        float t = sWm[tid];
        #pragma unroll
        for (int o = 16; o; o >>= 1) t = fmaxf(t, __shfl_xor_sync(0xffffffffu, t, o));
        if (tid == 0) sMx = t;
    }
    __syncthreads();
    return sMx;
}

// ============ Kernel B: finisher + 9 band phases, ONE 8-CTA cluster ============
__global__ void __launch_bounds__(NT, 1) __cluster_dims__(CSZ, 1, 1)
bands_kernel(const float * __restrict__ hm, float * __restrict__ out) {
    const int b = blockIdx.x;           // == cluster rank (single cluster)
    const int tid = threadIdx.x;
    const int lane = tid & 31;
    const int w = tid >> 5;
    __shared__ float s_ay, s_ay2[2];
    __shared__ float4 s_slot[2];        // published partial, double-buffered
    __shared__ float sRed[NW][3];
    const uint32_t slotAddr = smem_u32(&s_slot[0]);

    // ---- Phase 0 finisher (redundant in all 8 CTAs): merge 74 partials/channel ----
    for (int cc = 0; cc < 2; cc++) {
        float Mk = neg_inf(), S = 0.f, Sx = 0.f, Sy = 0.f;
        if (tid < CBLK) {
            float4 p = g_p0[cc * CBLK + tid];
            Mk = p.x; S = p.y; Sx = p.z; Sy = p.w;
        }
        float Mg = block_max_bcast(Mk);
        float e = (tid < CBLK) ? expf((Mk - Mg) * 100.f) : 0.f;
        S *= e; Sx *= e; Sy *= e;
        block_sum3(S, Sx, Sy);
        if (tid == 0) {
            float ax = Sx / S, ay = Sy / S;
            s_ay2[cc] = ay;
            if (b == 0) { out[(9 + cc) * 2 + 0] = ax; out[(9 + cc) * 2 + 1] = ay; }
        }
        __syncthreads();
    }
    float yA = s_ay2[0], yB = s_ay2[1];
    float dis = __fsub_rn(yB, yA), dsum = 0.f, dnum = 0.f;

    // ---------------- Band phases i = 8 .. 0 (1 cluster barrier each) ----------------
    for (int i = 8; i >= 0; i--) {
        // scalar band logic, redundant in all threads; __f*_rn blocks FMA contraction
        {
            float tmp = ceilf(__fsub_rn(yB, yA));
            if (fabsf(__fsub_rn(tmp, dis)) > __fmul_rn(0.35f, dis)) {
                dsum = __fadd_rn(dsum, tmp);
                dnum = __fadd_rn(dnum, 1.0f);
                dis  = __fdiv_rn(dsum, fmaxf(dnum, 1.0f));
            }
        }
        float last_y = floorf(yA);
        float t  = __fmul_rn(1.8f, dis);
        float sr = __fsub_rn(last_y, t);
        float end_y   = rintf(__fadd_rn(sr, t));   // round-half-even = jnp.round
        float start_y = rintf(sr);
        const int r0 = (start_y <= 0.f) ? 0  : (start_y >= (float)HH       ? HH     : (int)start_y);
        const int r1 = (end_y   <  0.f) ? -1 : (end_y   >= (float)(HH - 1) ? HH - 1 : (int)end_y);
        const int rows = r1 - r0 + 1;
        const int nelt = rows * 512;                // float4 count (<=0 if empty)
        const int par  = (8 - i) & 1;
        const float *chan = hm + (size_t)i * HH * WW;

        float Mpub, S = 0.f, Sx = 0.f, Sy = 0.f;    // partial (M scaled)
        if (nelt <= 2 * CSZ * NT) {
            // ---- fast path (rows <= 32): <=2 reg-resident tiles/thread ----
            const int g0 = b * NT + tid, g1 = g0 + CSZ * NT;
            const bool v0 = g0 < nelt, v1 = g1 < nelt;
            float4 A0, A1;
            float tm0 = neg_inf(), tm1 = neg_inf();
            if (v0) { A0 = reinterpret_cast<const float4*>(chan + (size_t)(r0 + (g0 >> 9)) * WW)[g0 & 511]; tm0 = fmax4(A0); }
            if (v1) { A1 = reinterpret_cast<const float4*>(chan + (size_t)(r0 + (g1 >> 9)) * WW)[g1 & 511]; tm1 = fmax4(A1); }
            float Mcta = cmax2(fmaxf(tm0, tm1));    // raw CTA max (2 bars)
            const float Ms  = Mcta * 100.f;
            const float thr = Mcta - 0.88f;
            if (__any_sync(0xffffffffu, tm0 > thr)) {
                if (v0) {
                    float e0 = expf(A0.x * 100.f - Ms), e1 = expf(A0.y * 100.f - Ms);
                    float e2 = expf(A0.z * 100.f - Ms), e3 = expf(A0.w * 100.f - Ms);
                    float es = (e0 + e1) + (e2 + e3);
                    float x0 = (float)((g0 & 511) << 2);
                    S  += es;
                    Sx += x0 * e0 + (x0 + 1.f) * e1 + (x0 + 2.f) * e2 + (x0 + 3.f) * e3;
                    Sy += (float)(r0 + (g0 >> 9)) * es;
                }
            }
            if (__any_sync(0xffffffffu, tm1 > thr)) {
                if (v1) {
                    float e0 = expf(A1.x * 100.f - Ms), e1 = expf(A1.y * 100.f - Ms);
                    float e2 = expf(A1.z * 100.f - Ms), e3 = expf(A1.w * 100.f - Ms);
                    float es = (e0 + e1) + (e2 + e3);
                    float x0 = (float)((g1 & 511) << 2);
                    S  += es;
                    Sx += x0 * e0 + (x0 + 1.f) * e1 + (x0 + 2.f) * e2 + (x0 + 3.f) * e3;
                    Sy += (float)(r0 + (g1 >> 9)) * es;
                }
            }
            Mpub = Ms;                              // -inf fine for empty CTAs
        } else {
            // ---- slow path (rows > 32, rare): per-thread online, scaled domain ----
            float Mt = neg_inf();
            for (int g = b * NT + tid; g < nelt; g += CSZ * NT) {
                int row = r0 + (g >> 9);
                float4 A = reinterpret_cast<const float4*>(chan + (size_t)row * WW)[g & 511];
                float q0 = A.x * 100.f, q1 = A.y * 100.f, q2 = A.z * 100.f, q3 = A.w * 100.f;
                float mr = fmaxf(fmaxf(q0, q1), fmaxf(q2, q3));
                if (mr > Mt) {
                    float r = expf(Mt - mr);        // expf(-inf)=0 first time
                    S *= r; Sx *= r; Sy *= r;
                    Mt = mr;
                }
                float e0 = expf(q0 - Mt), e1 = expf(q1 - Mt), e2 = expf(q2 - Mt), e3 = expf(q3 - Mt);
                float es = (e0 + e1) + (e2 + e3);
                float x0 = (float)((g & 511) << 2);
                S  += es;
                Sx += x0 * e0 + (x0 + 1.f) * e1 + (x0 + 2.f) * e2 + (x0 + 3.f) * e3;
                Sy += (float)row * es;
            }
            float Msc = cmax2(Mt);                  // scaled CTA max
            float e = (Mt == neg_inf()) ? 0.f : expf(Mt - Msc);
            S *= e; Sx *= e; Sy *= e;
            Mpub = Msc;
        }

        // CTA sum reduce (1 bar) + publish to own smem slot
        #pragma unroll
        for (int o = 16; o; o >>= 1) {
            S  += __shfl_xor_sync(0xffffffffu, S, o);
            Sx += __shfl_xor_sync(0xffffffffu, Sx, o);
            Sy += __shfl_xor_sync(0xffffffffu, Sy, o);
        }
        if (lane == 0) { sRed[w][0] = S; sRed[w][1] = Sx; sRed[w][2] = Sy; }
        __syncthreads();
        if (tid < 32) {
            S = sRed[tid][0]; Sx = sRed[tid][1]; Sy = sRed[tid][2];
            #pragma unroll
            for (int o = 16; o; o >>= 1) {
                S  += __shfl_xor_sync(0xffffffffu, S, o);
                Sx += __shfl_xor_sync(0xffffffffu, Sx, o);
                Sy += __shfl_xor_sync(0xffffffffu, Sy, o);
            }
            if (tid == 0) s_slot[par] = make_float4(Mpub, S, Sx, Sy);
        }
        CLUSTER_BAR();                              // smem visible cluster-wide

        // gather 8 partials via DSMEM + single-warp finisher + closed-form tail
        if (tid < 32) {
            float Mk = neg_inf(), T = 0.f, Tx = 0.f, Ty = 0.f;
            if (tid < CSZ) {
                uint32_t a = mapa_u32(slotAddr + (uint32_t)(par * 16), (uint32_t)tid);
                Mk = ld_clu_f32(a);
                T  = ld_clu_f32(a + 4);
                Tx = ld_clu_f32(a + 8);
                Ty = ld_clu_f32(a + 12);
            }
            float Mg = Mk;
            #pragma unroll
            for (int o = 16; o; o >>= 1) Mg = fmaxf(Mg, __shfl_xor_sync(0xffffffffu, Mg, o));
            float e2 = (Mk == neg_inf()) ? 0.f : expf(Mk - Mg);
            T *= e2; Tx *= e2; Ty *= e2;
            #pragma unroll
            for (int o = 16; o; o >>= 1) {
                T  += __shfl_xor_sync(0xffffffffu, T, o);
                Tx += __shfl_xor_sync(0xffffffffu, Tx, o);
                Ty += __shfl_xor_sync(0xffffffffu, Ty, o);
            }
            if (tid == 0) {
                float Rn = (rows > 0) ? (float)rows : 0.f;
                float m;
                if (Rn >= 2048.f)      m = Mg;               // band covers everything
                else if (Rn > 0.f)     m = fmaxf(Mg, 0.f);   // zeros exist outside band
                else                   m = 0.f;              // empty band: all-zero map
                float sc = (Rn > 0.f) ? expf(Mg - m) : 0.f;
                T *= sc; Tx *= sc; Ty *= sc;
                if (Rn < 2048.f) {
                    const float NTOT  = 4194304.f;      // H*W
                    const float SXROW = 2096128.f;      // W*(W-1)/2
                    const float SXTOT = 4292870144.f;   // H * SXROW
                    const float SYTOT = 4292870144.f;   // W * H*(H-1)/2
                    float e0 = expf(-m);
                    T  += (NTOT  - Rn * 2048.f) * e0;
                    Tx += (SXTOT - Rn * SXROW ) * e0;
                    Ty += (SYTOT - 2048.f * (0.5f * (float)(r0 + r1) * Rn)) * e0;
                }
                float ax = Tx / T, ay = Ty / T;
                s_ay = ay;
                if (b == 0) { out[i * 2 + 0] = ax; out[i * 2 + 1] = ay; }
            }
        }
        __syncthreads();
        yB = yA;
        yA = s_ay;
    }

    // no CTA may exit while peers might still read its smem
    CLUSTER_BAR();
}

extern "C" void kernel_launch(void* const* d_in, const int* in_sizes, int n_in,
                              void* d_out, int out_size) {
    const float *hm = (const float*)d_in[0];
    float *out = (float*)d_out;
    (void)in_sizes; (void)n_in; (void)out_size;

    phase0_kernel<<<NB, NT>>>(hm);
    bands_kernel<<<CSZ, NT>>>(hm, out);
}